// round 2
// baseline (speedup 1.0000x reference)
#include <cuda_runtime.h>
#include <cuda_bf16.h>

// h_new[n, j] = h_prev[n, j] + sum_k W[Z[n]][j][k] * m_curr[n][k]
// N = 16384, D = 128, S = 119, atom_types sorted.
//
// Round 2: barrier-free mainloop.
//  - Block = 64 nodes, 256 threads (8 warps). One __syncthreads total (m tile).
//  - In-warp k-split: lane = 2*jj + h.  j = warp*16 + jj (warp covers 16 outputs),
//    h in {0,1} selects k-half [h*64, h*64+64). Each lane caches 64 W floats in regs.
//  - Segment detection: 64 atom types preloaded into 2 regs/lane, boundaries found
//    with ballots (no gmem binary search, no smem, no barriers).
//  - Reduction: one shfl_xor(1); both lanes end with the full sum, then split the
//    epilogue stores across h (h=0 -> nodes 0..3 of batch, h=1 -> 4..7).

#define N_NODES  16384
#define D        128
#define NB       64
#define NT       8
#define THREADS  256

__global__ void __launch_bounds__(THREADS, 2)
element_update_kernel(const float* __restrict__ h_prev,
                      const float* __restrict__ m_curr,
                      const int*   __restrict__ atom_types,
                      const float* __restrict__ weight,
                      float*       __restrict__ out)
{
    __shared__ float m_s[NB + NT][D];

    const int t    = threadIdx.x;
    const int lane = t & 31;
    const int warp = t >> 5;            // 0..7
    const int jj   = lane >> 1;         // 0..15
    const int h    = lane & 1;          // k-half
    const int j    = warp * 16 + jj;    // output index 0..127
    const int n0   = blockIdx.x * NB;

    // ---- load m tile (coalesced float4) + zero the NT padding rows ----
    {
        const float4* src = (const float4*)(m_curr + (size_t)n0 * D);
        float4* dst = (float4*)(&m_s[0][0]);
        #pragma unroll 4
        for (int i = t; i < NB * D / 4; i += THREADS) dst[i] = src[i];
        float4 z4 = make_float4(0.f, 0.f, 0.f, 0.f);
        for (int i = t; i < NT * D / 4; i += THREADS)
            ((float4*)(&m_s[NB][0]))[i] = z4;
    }

    // ---- preload the 64 species ids of this block into 2 regs/lane ----
    const int ty0 = atom_types[n0 + lane];
    const int ty1 = atom_types[n0 + 32 + lane];

    __syncthreads();   // the ONLY block barrier

    int s = 0;
    while (s < NB) {
        // species of node s (uniform across warp)
        const int z = (s < 32) ? __shfl_sync(0xffffffffu, ty0, s)
                               : __shfl_sync(0xffffffffu, ty1, s - 32);

        // segment end: first index > s with a different type (ballot scan)
        unsigned b0 = __ballot_sync(0xffffffffu, ty0 != z);
        unsigned b1 = __ballot_sync(0xffffffffu, ty1 != z);
        if (s < 32) {
            b0 &= (s < 31) ? (0xffffffffu << (s + 1)) : 0u;
        } else {
            b0 = 0u;
            int sp = s - 32;
            b1 &= (sp < 31) ? (0xffffffffu << (sp + 1)) : 0u;
        }
        const int e = b0 ? (__ffs(b0) - 1) : (b1 ? (32 + __ffs(b1) - 1) : NB);

        // ---- cache this lane's 64-float half-row of W[z] in registers ----
        float w[64];
        {
            const float4* wp = (const float4*)
                (weight + (size_t)z * D * D + (size_t)j * D + h * 64);
            #pragma unroll
            for (int i = 0; i < 16; i++) ((float4*)w)[i] = wp[i];
        }

        for (int nb = s; nb < e; nb += NT) {
            // prefetch h_prev for this batch (overlaps the FFMA block below)
            float hp[4];
            #pragma unroll
            for (int p = 0; p < 4; p++) {
                int node = nb + h * 4 + p;
                hp[p] = (node < e)
                      ? h_prev[(size_t)(n0 + node) * D + j] : 0.0f;
            }

            float acc[NT];
            #pragma unroll
            for (int n = 0; n < NT; n++) acc[n] = 0.0f;

            // 16 k-chunks x 8 nodes: 1 broadcast LDS.128 + 4 FFMA each
            #pragma unroll
            for (int kk = 0; kk < 16; kk++) {
                #pragma unroll
                for (int n = 0; n < NT; n++) {
                    float4 m4 = ((const float4*)&m_s[nb + n][h * 64])[kk];
                    acc[n] = fmaf(w[4 * kk + 0], m4.x, acc[n]);
                    acc[n] = fmaf(w[4 * kk + 1], m4.y, acc[n]);
                    acc[n] = fmaf(w[4 * kk + 2], m4.z, acc[n]);
                    acc[n] = fmaf(w[4 * kk + 3], m4.w, acc[n]);
                }
            }

            // in-warp k-half reduction: pair (2jj, 2jj+1) -> both get full sum
            #pragma unroll
            for (int n = 0; n < NT; n++)
                acc[n] += __shfl_xor_sync(0xffffffffu, acc[n], 1);

            // epilogue: h=0 stores nodes nb..nb+3, h=1 stores nb+4..nb+7
            #pragma unroll
            for (int p = 0; p < 4; p++) {
                int node = nb + h * 4 + p;
                if (node < e)
                    out[(size_t)(n0 + node) * D + j] = hp[p] + acc[h * 4 + p];
            }
        }
        s = e;
    }
}

extern "C" void kernel_launch(void* const* d_in, const int* in_sizes, int n_in,
                              void* d_out, int out_size)
{
    const float* h_prev     = (const float*)d_in[0];
    const float* m_curr     = (const float*)d_in[1];
    const int*   atom_types = (const int*)  d_in[2];
    const float* weight     = (const float*)d_in[3];
    float*       out        = (float*)d_out;

    dim3 grid(N_NODES / NB);
    dim3 block(THREADS);
    element_update_kernel<<<grid, block>>>(h_prev, m_curr, atom_types, weight, out);
}

// round 5
// speedup vs baseline: 1.3857x; 1.3857x over previous
#include <cuda_runtime.h>
#include <cuda_bf16.h>

// h_new[n, j] = h_prev[n, j] + sum_k W[Z[n]][j][k] * m_curr[n][k]
// N = 16384, D = 128, S = 119, atom_types sorted.
//
// Round 3: LDS-pressure fix.
//  - Thread owns 2 j rows x 32-k quarter: one LDS.128 feeds 8 FFMA (was 4).
//  - XOR-swizzled m tile: the 4 k-quarter addresses per warp hit distinct
//    bank groups (unswizzled they alias mod 128B -> 4-way conflict).
//  - Barrier-free mainloop, ballot segment detection, shfl_xor k-reduction.

#define N_NODES  16384
#define D        128
#define NB       64
#define NT       8
#define THREADS  256

__global__ void __launch_bounds__(THREADS, 2)
element_update_kernel(const float* __restrict__ h_prev,
                      const float* __restrict__ m_curr,
                      const int*   __restrict__ atom_types,
                      const float* __restrict__ weight,
                      float*       __restrict__ out)
{
    // m tile as float4 units: 32 units per node row, XOR-swizzled within row
    __shared__ float4 m_s[(NB + NT) * 32];

    const int t    = threadIdx.x;
    const int lane = t & 31;
    const int kg   = t & 3;            // k-quarter: k in [kg*32, kg*32+32)
    const int jg   = t >> 2;           // 0..63 -> j pair (2*jg, 2*jg+1)
    const int j0   = jg * 2;
    const int n0   = blockIdx.x * NB;

    // ---- fill m tile (coalesced read, swizzled write) + zero padding ----
    {
        const float4* src = (const float4*)(m_curr + (size_t)n0 * D);
        #pragma unroll 4
        for (int i = t; i < NB * 32; i += THREADS) {
            int node = i >> 5, u = i & 31;
            int p = u ^ ((u >> 3) << 1);           // in-block xor: conflict-free
            m_s[node * 32 + p] = src[i];
        }
        float4 z4 = make_float4(0.f, 0.f, 0.f, 0.f);
        for (int i = t; i < NT * 32; i += THREADS)
            m_s[NB * 32 + i] = z4;
    }

    // ---- preload the 64 species ids of this block into 2 regs/lane ----
    const int ty0 = atom_types[n0 + lane];
    const int ty1 = atom_types[n0 + 32 + lane];

    __syncthreads();   // the ONLY block barrier

    int s = 0;
    while (s < NB) {
        const int z = (s < 32) ? __shfl_sync(0xffffffffu, ty0, s)
                               : __shfl_sync(0xffffffffu, ty1, s - 32);

        unsigned b0 = __ballot_sync(0xffffffffu, ty0 != z);
        unsigned b1 = __ballot_sync(0xffffffffu, ty1 != z);
        if (s < 32) {
            b0 &= (s < 31) ? (0xffffffffu << (s + 1)) : 0u;
        } else {
            b0 = 0u;
            int sp = s - 32;
            b1 &= (sp < 31) ? (0xffffffffu << (sp + 1)) : 0u;
        }
        const int e = b0 ? (__ffs(b0) - 1) : (b1 ? (32 + __ffs(b1) - 1) : NB);

        // ---- cache 2 W rows x 32-k quarter in registers (64 floats) ----
        float w0[32], w1[32];
        {
            const float4* wp0 = (const float4*)
                (weight + (size_t)z * D * D + (size_t)j0 * D + kg * 32);
            const float4* wp1 = (const float4*)((const float*)wp0 + D);
            #pragma unroll
            for (int i = 0; i < 8; i++) {
                ((float4*)w0)[i] = wp0[i];
                ((float4*)w1)[i] = wp1[i];
            }
        }

        for (int nb = s; nb < e; nb += NT) {
            // prefetch h_prev for the 2 nodes this lane will store
            const int nA = nb + kg, nBn = nb + kg + 4;
            float2 hpA = make_float2(0.f, 0.f), hpB = make_float2(0.f, 0.f);
            if (nA  < e) hpA = *(const float2*)&h_prev[(size_t)(n0 + nA)  * D + j0];
            if (nBn < e) hpB = *(const float2*)&h_prev[(size_t)(n0 + nBn) * D + j0];

            float a0[NT], a1[NT];
            #pragma unroll
            for (int n = 0; n < NT; n++) { a0[n] = 0.f; a1[n] = 0.f; }

            // 8 k-chunks x 8 nodes: 1 swizzled broadcast LDS.128 + 8 FFMA
            #pragma unroll
            for (int kk = 0; kk < 8; kk++) {
                const int pu = kg * 8 + (kk ^ (kg << 1));  // swizzled unit
                #pragma unroll
                for (int n = 0; n < NT; n++) {
                    float4 m4 = m_s[(nb + n) * 32 + pu];
                    a0[n] = fmaf(w0[4 * kk + 0], m4.x, a0[n]);
                    a0[n] = fmaf(w0[4 * kk + 1], m4.y, a0[n]);
                    a0[n] = fmaf(w0[4 * kk + 2], m4.z, a0[n]);
                    a0[n] = fmaf(w0[4 * kk + 3], m4.w, a0[n]);
                    a1[n] = fmaf(w1[4 * kk + 0], m4.x, a1[n]);
                    a1[n] = fmaf(w1[4 * kk + 1], m4.y, a1[n]);
                    a1[n] = fmaf(w1[4 * kk + 2], m4.z, a1[n]);
                    a1[n] = fmaf(w1[4 * kk + 3], m4.w, a1[n]);
                }
            }

            // reduce across the 4 k-quarter lanes (lane bits 0..1)
            #pragma unroll
            for (int n = 0; n < NT; n++) {
                a0[n] += __shfl_xor_sync(0xffffffffu, a0[n], 1);
                a0[n] += __shfl_xor_sync(0xffffffffu, a0[n], 2);
                a1[n] += __shfl_xor_sync(0xffffffffu, a1[n], 1);
                a1[n] += __shfl_xor_sync(0xffffffffu, a1[n], 2);
            }

            // lane kg stores nodes nb+kg and nb+kg+4 (constant-index select)
            float r0 = 0.f, r1 = 0.f, s0 = 0.f, s1 = 0.f;
            #pragma unroll
            for (int p = 0; p < 4; p++)
                if (kg == p) {
                    r0 = a0[p];     r1 = a1[p];
                    s0 = a0[p + 4]; s1 = a1[p + 4];
                }
            if (nA  < e)
                *(float2*)&out[(size_t)(n0 + nA)  * D + j0] =
                    make_float2(hpA.x + r0, hpA.y + r1);
            if (nBn < e)
                *(float2*)&out[(size_t)(n0 + nBn) * D + j0] =
                    make_float2(hpB.x + s0, hpB.y + s1);
        }
        s = e;
    }
}

extern "C" void kernel_launch(void* const* d_in, const int* in_sizes, int n_in,
                              void* d_out, int out_size)
{
    const float* h_prev     = (const float*)d_in[0];
    const float* m_curr     = (const float*)d_in[1];
    const int*   atom_types = (const int*)  d_in[2];
    const float* weight     = (const float*)d_in[3];
    float*       out        = (float*)d_out;

    dim3 grid(N_NODES / NB);
    dim3 block(THREADS);
    element_update_kernel<<<grid, block>>>(h_prev, m_curr, atom_types, weight, out);
}

// round 8
// speedup vs baseline: 2.7736x; 2.0017x over previous
#include <cuda_runtime.h>
#include <cuda_bf16.h>
#include <cstdint>

// h_new[n, j] = h_prev[n, j] + sum_k W[Z[n]][j][k] * m_curr[n][k]
// N = 16384, D = 128, S = 119, atom_types sorted.
//
// Round 7: mma.sync tf32 (baseline PTX ISA -- tcgen05 is rejected by this
// harness's compute_103 virtual target).
//  - Block = 128 nodes, 8 warps; warp owns 32 rows x 64 cols (2 m16 x 8 n8
//    tiles), 64 accumulator regs, m16n8k8 tf32 HMMA.
//  - m tile + W[z] in smem, tf32 pre-rounded (cvt.rna), row pitch 132 floats
//    -> conflict-free fragment gathers.
//  - Sorted types -> block segment loop; A rows outside the live segment are
//    zeroed via predicated fragment loads; accumulators sum across segments.

#define N_NODES  16384
#define D        128
#define NB       128
#define THREADS  256
#define PITCH    132          // smem row pitch in floats (conflict-free)

__device__ __forceinline__ uint32_t cvt_tf32(float f) {
    uint32_t r;
    asm("cvt.rna.tf32.f32 %0, %1;" : "=r"(r) : "f"(f));
    return r;
}

__device__ __forceinline__ void mma_tf32(float& c0, float& c1, float& c2, float& c3,
                                         uint32_t a0, uint32_t a1, uint32_t a2, uint32_t a3,
                                         uint32_t b0, uint32_t b1) {
    asm volatile(
        "mma.sync.aligned.m16n8k8.row.col.f32.tf32.tf32.f32 "
        "{%0,%1,%2,%3}, {%4,%5,%6,%7}, {%8,%9}, {%0,%1,%2,%3};"
        : "+f"(c0), "+f"(c1), "+f"(c2), "+f"(c3)
        : "r"(a0), "r"(a1), "r"(a2), "r"(a3), "r"(b0), "r"(b1));
}

__global__ void __launch_bounds__(THREADS, 1)
element_update_kernel(const float* __restrict__ h_prev,
                      const float* __restrict__ m_curr,
                      const int*   __restrict__ atom_types,
                      const float* __restrict__ weight,
                      float*       __restrict__ out)
{
    extern __shared__ char smem_raw[];
    uint32_t* m_s  = (uint32_t*)smem_raw;                      // [128][PITCH] tf32
    uint32_t* w_s  = m_s + NB * PITCH;                          // [128][PITCH] tf32
    int*      types_s = (int*)(w_s + NB * PITCH);               // [128]
    unsigned* masks_s = (unsigned*)(types_s + NB);              // [4]

    const int t    = threadIdx.x;
    const int warp = t >> 5;
    const int lane = t & 31;
    const int qr   = lane >> 2;          // 0..7  (fragment row group)
    const int qc   = lane & 3;           // 0..3  (fragment col-in-group)
    const int m0   = (warp & 3) * 32;    // warp's row base
    const int nc0  = (warp >> 2) * 64;   // warp's col base
    const int n0   = blockIdx.x * NB;

    // ---- m tile -> smem (tf32) ----
    for (int i = t; i < NB * 32; i += THREADS) {
        int row = i >> 5, u = i & 31;
        float4 v = *(const float4*)(m_curr + (size_t)(n0 + row) * D + u * 4);
        uint32_t* dst = &m_s[row * PITCH + u * 4];
        dst[0] = cvt_tf32(v.x); dst[1] = cvt_tf32(v.y);
        dst[2] = cvt_tf32(v.z); dst[3] = cvt_tf32(v.w);
    }

    // ---- types + per-warp boundary masks ----
    int myty = 0;
    if (t < NB) { myty = atom_types[n0 + t]; types_s[t] = myty; }
    __syncthreads();
    if (t < NB) {
        int flag = (t == 0) || (types_s[t - 1] != myty);
        unsigned b = __ballot_sync(0xffffffffu, flag);
        if (lane == 0) masks_s[warp] = b;
    }
    __syncthreads();

    // ---- accumulators: 2 m-tiles x 8 n-tiles x 4 ----
    float acc[2][8][4];
    #pragma unroll
    for (int mt = 0; mt < 2; mt++)
        #pragma unroll
        for (int nt = 0; nt < 8; nt++)
            #pragma unroll
            for (int q = 0; q < 4; q++) acc[mt][nt][q] = 0.0f;

    // ---- segment loop ----
    int s = 0;
    while (s < NB) {
        const int z = types_s[s];
        int e = NB;
        {
            int w0 = s >> 5, b0 = s & 31;
            unsigned m = masks_s[w0] & ((b0 == 31) ? 0u : (0xffffffffu << (b0 + 1)));
            if (m) e = w0 * 32 + __ffs(m) - 1;
            else {
                for (int w = w0 + 1; w < 4; w++)
                    if (masks_s[w]) { e = w * 32 + __ffs(masks_s[w]) - 1; break; }
            }
        }

        // load W[z] -> w_s (tf32)
        {
            const float* wz = weight + (size_t)z * D * D;
            for (int i = t; i < NB * 32; i += THREADS) {
                int row = i >> 5, u = i & 31;
                float4 v = *(const float4*)(wz + (size_t)row * D + u * 4);
                uint32_t* dst = &w_s[row * PITCH + u * 4];
                dst[0] = cvt_tf32(v.x); dst[1] = cvt_tf32(v.y);
                dst[2] = cvt_tf32(v.z); dst[3] = cvt_tf32(v.w);
            }
        }
        __syncthreads();

        if (e > m0 && s < m0 + 32) {      // warp's rows intersect [s, e)
            // per-row in-segment predicates (4 row positions)
            const int r0 = m0 + qr, r1 = r0 + 8, r2 = r0 + 16, r3 = r0 + 24;
            const bool p0 = (r0 >= s) & (r0 < e), p1 = (r1 >= s) & (r1 < e);
            const bool p2 = (r2 >= s) & (r2 < e), p3 = (r3 >= s) & (r3 < e);

            #pragma unroll
            for (int ks = 0; ks < 16; ks++) {
                const int k0 = ks * 8;
                // A fragments (predicated zero outside segment)
                uint32_t aA0 = p0 ? m_s[r0 * PITCH + k0 + qc]     : 0u;
                uint32_t aA1 = p1 ? m_s[r1 * PITCH + k0 + qc]     : 0u;
                uint32_t aA2 = p0 ? m_s[r0 * PITCH + k0 + qc + 4] : 0u;
                uint32_t aA3 = p1 ? m_s[r1 * PITCH + k0 + qc + 4] : 0u;
                uint32_t aB0 = p2 ? m_s[r2 * PITCH + k0 + qc]     : 0u;
                uint32_t aB1 = p3 ? m_s[r3 * PITCH + k0 + qc]     : 0u;
                uint32_t aB2 = p2 ? m_s[r2 * PITCH + k0 + qc + 4] : 0u;
                uint32_t aB3 = p3 ? m_s[r3 * PITCH + k0 + qc + 4] : 0u;

                #pragma unroll
                for (int nt = 0; nt < 8; nt++) {
                    const int nrow = nc0 + nt * 8 + qr;
                    uint32_t b0 = w_s[nrow * PITCH + k0 + qc];
                    uint32_t b1 = w_s[nrow * PITCH + k0 + qc + 4];
                    mma_tf32(acc[0][nt][0], acc[0][nt][1], acc[0][nt][2], acc[0][nt][3],
                             aA0, aA1, aA2, aA3, b0, b1);
                    mma_tf32(acc[1][nt][0], acc[1][nt][1], acc[1][nt][2], acc[1][nt][3],
                             aB0, aB1, aB2, aB3, b0, b1);
                }
            }
        }
        __syncthreads();   // protect w_s before next segment overwrite
        s = e;
    }

    // ---- epilogue: add h_prev, store (float2 per fragment row) ----
    #pragma unroll
    for (int mt = 0; mt < 2; mt++) {
        #pragma unroll
        for (int nt = 0; nt < 8; nt++) {
            const int col = nc0 + nt * 8 + qc * 2;
            const int ra  = m0 + mt * 16 + qr;
            const int rb  = ra + 8;
            const size_t ia = (size_t)(n0 + ra) * D + col;
            const size_t ib = (size_t)(n0 + rb) * D + col;
            float2 ha = *(const float2*)(h_prev + ia);
            float2 hb = *(const float2*)(h_prev + ib);
            *(float2*)(out + ia) = make_float2(ha.x + acc[mt][nt][0],
                                               ha.y + acc[mt][nt][1]);
            *(float2*)(out + ib) = make_float2(hb.x + acc[mt][nt][2],
                                               hb.y + acc[mt][nt][3]);
        }
    }
}

#define SMEM_TOTAL ((2 * NB * PITCH) * 4 + NB * 4 + 16)

extern "C" void kernel_launch(void* const* d_in, const int* in_sizes, int n_in,
                              void* d_out, int out_size)
{
    const float* h_prev     = (const float*)d_in[0];
    const float* m_curr     = (const float*)d_in[1];
    const int*   atom_types = (const int*)  d_in[2];
    const float* weight     = (const float*)d_in[3];
    float*       out        = (float*)d_out;

    cudaFuncSetAttribute(element_update_kernel,
                         cudaFuncAttributeMaxDynamicSharedMemorySize, SMEM_TOTAL);
    dim3 grid(N_NODES / NB);   // 128 blocks
    dim3 block(THREADS);
    element_update_kernel<<<grid, block, SMEM_TOTAL>>>(h_prev, m_curr, atom_types,
                                                       weight, out);
}

// round 13
// speedup vs baseline: 3.1157x; 1.1233x over previous
#include <cuda_runtime.h>
#include <cuda_bf16.h>
#include <cstdint>

// h_new[n, j] = h_prev[n, j] + sum_k W[Z[n]][j][k] * m_curr[n][k]
// N = 16384, D = 128, S = 119, atom_types sorted.
//
// Round 8: occupancy/overlap fix for the mma.sync tf32 kernel.
//  - NB=64, grid=256 (all SMs), smem ~102KB -> 2 blocks/SM, 4 warps/SMSP.
//  - 8 warps/block; warp = 16 rows x 64 cols (2x m16 row-halves x 8 n8 tiles).
//  - Seg-0 W fill overlaps m-tile fill (z0 read directly, single barrier).
//  - Predicated A fragments zero rows outside the live segment; accumulators
//    sum across segments (each row belongs to exactly one).

#define N_NODES  16384
#define D        128
#define NB       64
#define THREADS  256
#define PITCH    132          // smem row pitch in floats (conflict-free)

__device__ __forceinline__ uint32_t cvt_tf32(float f) {
    uint32_t r;
    asm("cvt.rna.tf32.f32 %0, %1;" : "=r"(r) : "f"(f));
    return r;
}

__device__ __forceinline__ void mma_tf32(float& c0, float& c1, float& c2, float& c3,
                                         uint32_t a0, uint32_t a1, uint32_t a2, uint32_t a3,
                                         uint32_t b0, uint32_t b1) {
    asm volatile(
        "mma.sync.aligned.m16n8k8.row.col.f32.tf32.tf32.f32 "
        "{%0,%1,%2,%3}, {%4,%5,%6,%7}, {%8,%9}, {%0,%1,%2,%3};"
        : "+f"(c0), "+f"(c1), "+f"(c2), "+f"(c3)
        : "r"(a0), "r"(a1), "r"(a2), "r"(a3), "r"(b0), "r"(b1));
}

__global__ void __launch_bounds__(THREADS, 2)
element_update_kernel(const float* __restrict__ h_prev,
                      const float* __restrict__ m_curr,
                      const int*   __restrict__ atom_types,
                      const float* __restrict__ weight,
                      float*       __restrict__ out)
{
    extern __shared__ char smem_raw[];
    uint32_t* m_s     = (uint32_t*)smem_raw;              // [64][PITCH] tf32
    uint32_t* w_s     = m_s + NB * PITCH;                 // [128][PITCH] tf32
    int*      types_s = (int*)(w_s + D * PITCH);          // [64]
    unsigned* masks_s = (unsigned*)(types_s + NB);        // [2]

    const int t    = threadIdx.x;
    const int warp = t >> 5;
    const int lane = t & 31;
    const int qr   = lane >> 2;          // 0..7
    const int qc   = lane & 3;           // 0..3
    const int m0   = (warp & 3) * 16;    // warp's row base (4 groups x 16)
    const int nc0  = (warp >> 2) * 64;   // warp's col base (2 halves)
    const int n0   = blockIdx.x * NB;

    // ---- segment-0 species (broadcast load, no sync needed) ----
    const int z0 = atom_types[n0];

    // ---- W[z0] -> w_s (tf32) : overlaps with m fill below ----
    {
        const float* wz = weight + (size_t)z0 * D * D;
        #pragma unroll 4
        for (int i = t; i < D * 32; i += THREADS) {
            int row = i >> 5, u = i & 31;
            float4 v = *(const float4*)(wz + (size_t)row * D + u * 4);
            uint32_t* dst = &w_s[row * PITCH + u * 4];
            dst[0] = cvt_tf32(v.x); dst[1] = cvt_tf32(v.y);
            dst[2] = cvt_tf32(v.z); dst[3] = cvt_tf32(v.w);
        }
    }
    // ---- m tile -> smem (tf32) ----
    #pragma unroll 4
    for (int i = t; i < NB * 32; i += THREADS) {
        int row = i >> 5, u = i & 31;
        float4 v = *(const float4*)(m_curr + (size_t)(n0 + row) * D + u * 4);
        uint32_t* dst = &m_s[row * PITCH + u * 4];
        dst[0] = cvt_tf32(v.x); dst[1] = cvt_tf32(v.y);
        dst[2] = cvt_tf32(v.z); dst[3] = cvt_tf32(v.w);
    }

    // ---- types + boundary masks (2 warps' worth of rows) ----
    int myty = 0;
    if (t < NB) { myty = atom_types[n0 + t]; types_s[t] = myty; }
    if (t < NB) {
        // need neighbor's type: shuffle covers within-warp; lane 0 of warp 1
        // reads types via shfl from its own load order, so use gmem value:
        int prev = (t == 0) ? (myty + 1) : atom_types[n0 + t - 1];
        int flag = (prev != myty);
        unsigned b = __ballot_sync(0xffffffffu, flag);
        if (lane == 0) masks_s[warp] = b;
    }
    __syncthreads();   // w_s(z0), m_s, types, masks all ready

    // ---- accumulators: 8 n-tiles x 4 ----
    float acc[8][4];
    #pragma unroll
    for (int nt = 0; nt < 8; nt++)
        #pragma unroll
        for (int q = 0; q < 4; q++) acc[nt][q] = 0.0f;

    // ---- segment loop ----
    int s = 0, first = 1;
    while (s < NB) {
        const int z = types_s[s];
        int e = NB;
        {
            int w0 = s >> 5, b0 = s & 31;
            unsigned m = masks_s[w0] & ((b0 == 31) ? 0u : (0xffffffffu << (b0 + 1)));
            if (m) e = w0 * 32 + __ffs(m) - 1;
            else if (w0 == 0 && masks_s[1]) e = 32 + __ffs(masks_s[1]) - 1;
        }

        if (!first) {
            __syncthreads();   // prior MMA readers done with w_s
            const float* wz = weight + (size_t)z * D * D;
            #pragma unroll 4
            for (int i = t; i < D * 32; i += THREADS) {
                int row = i >> 5, u = i & 31;
                float4 v = *(const float4*)(wz + (size_t)row * D + u * 4);
                uint32_t* dst = &w_s[row * PITCH + u * 4];
                dst[0] = cvt_tf32(v.x); dst[1] = cvt_tf32(v.y);
                dst[2] = cvt_tf32(v.z); dst[3] = cvt_tf32(v.w);
            }
            __syncthreads();
        }

        if (e > m0 && s < m0 + 16) {     // warp's 16 rows intersect [s, e)
            const int r0 = m0 + qr, r1 = r0 + 8;
            const bool p0 = (r0 >= s) & (r0 < e);
            const bool p1 = (r1 >= s) & (r1 < e);

            #pragma unroll
            for (int ks = 0; ks < 16; ks++) {
                const int k0 = ks * 8;
                uint32_t a0 = p0 ? m_s[r0 * PITCH + k0 + qc]     : 0u;
                uint32_t a1 = p1 ? m_s[r1 * PITCH + k0 + qc]     : 0u;
                uint32_t a2 = p0 ? m_s[r0 * PITCH + k0 + qc + 4] : 0u;
                uint32_t a3 = p1 ? m_s[r1 * PITCH + k0 + qc + 4] : 0u;

                #pragma unroll
                for (int nt = 0; nt < 8; nt++) {
                    const int nrow = nc0 + nt * 8 + qr;
                    uint32_t b0 = w_s[nrow * PITCH + k0 + qc];
                    uint32_t b1 = w_s[nrow * PITCH + k0 + qc + 4];
                    mma_tf32(acc[nt][0], acc[nt][1], acc[nt][2], acc[nt][3],
                             a0, a1, a2, a3, b0, b1);
                }
            }
        }
        first = 0;
        s = e;
    }

    // ---- epilogue: add h_prev, store ----
    const int ra = m0 + qr, rb = ra + 8;
    #pragma unroll
    for (int nt = 0; nt < 8; nt++) {
        const int col = nc0 + nt * 8 + qc * 2;
        const size_t ia = (size_t)(n0 + ra) * D + col;
        const size_t ib = (size_t)(n0 + rb) * D + col;
        float2 ha = *(const float2*)(h_prev + ia);
        float2 hb = *(const float2*)(h_prev + ib);
        *(float2*)(out + ia) = make_float2(ha.x + acc[nt][0], ha.y + acc[nt][1]);
        *(float2*)(out + ib) = make_float2(hb.x + acc[nt][2], hb.y + acc[nt][3]);
    }
}

#define SMEM_TOTAL ((NB * PITCH + D * PITCH) * 4 + NB * 4 + 32)

extern "C" void kernel_launch(void* const* d_in, const int* in_sizes, int n_in,
                              void* d_out, int out_size)
{
    const float* h_prev     = (const float*)d_in[0];
    const float* m_curr     = (const float*)d_in[1];
    const int*   atom_types = (const int*)  d_in[2];
    const float* weight     = (const float*)d_in[3];
    float*       out        = (float*)d_out;

    cudaFuncSetAttribute(element_update_kernel,
                         cudaFuncAttributeMaxDynamicSharedMemorySize, SMEM_TOTAL);
    dim3 grid(N_NODES / NB);   // 256 blocks
    dim3 block(THREADS);
    element_update_kernel<<<grid, block, SMEM_TOTAL>>>(h_prev, m_curr, atom_types,
                                                       weight, out);
}